// round 1
// baseline (speedup 1.0000x reference)
#include <cuda_runtime.h>
#include <math.h>

// out = gelu_tanh(x) * gate
// gate = 1 + exp(log_alpha) * tanh(exp(log_sigma) * surp)
// surp = mean over all (token,feature) of 2*|rank/(N-1) - 0.5| where rank is the
//        double-argsort rank along the token axis (N = B*T). Since argsort(argsort)
//        is always a permutation of 0..N-1 per column (independent of data/ties),
//        surp = N / (2*(N-1)) exactly — a data-independent constant.

__device__ __forceinline__ float gelu_tanh_f(float x) {
    const float c0 = 0.7978845608028654f;   // sqrt(2/pi)
    const float c1 = 0.044715f;
    float x3 = x * x * x;
    float t = tanhf(c0 * fmaf(c1, x3, x));
    return 0.5f * x * (1.0f + t);
}

__global__ void __launch_bounds__(512)
gelu_gate_kernel(const float4* __restrict__ x,
                 const float* __restrict__ log_alpha,
                 const float* __restrict__ log_sigma,
                 float4* __restrict__ out,
                 int n4, float surp) {
    int i = blockIdx.x * blockDim.x + threadIdx.x;
    if (i >= n4) return;

    // Uniform scalar loads: L1-broadcast, effectively free.
    float alpha = __expf(log_alpha[0]);
    float sigma = __expf(log_sigma[0]);
    float gate  = fmaf(alpha, tanhf(sigma * surp), 1.0f);

    float4 v = x[i];
    float4 r;
    r.x = gelu_tanh_f(v.x) * gate;
    r.y = gelu_tanh_f(v.y) * gate;
    r.z = gelu_tanh_f(v.z) * gate;
    r.w = gelu_tanh_f(v.w) * gate;
    out[i] = r;
}

extern "C" void kernel_launch(void* const* d_in, const int* in_sizes, int n_in,
                              void* d_out, int out_size) {
    const float* x         = (const float*)d_in[0];
    const float* log_alpha = (const float*)d_in[1];
    const float* log_sigma = (const float*)d_in[2];
    float* out             = (float*)d_out;

    long long n = in_sizes[0];          // B*T*D = 4*2048*4096
    const long long D = 4096;
    long long N = n / D;                // token count B*T = 8192
    // mean extremeness of a full permutation of 0..N-1 (even N): N / (2*(N-1))
    float surp = (float)((double)N / (2.0 * (double)(N - 1)));

    int n4 = (int)(n / 4);              // n divisible by 4
    int threads = 512;
    int blocks = (n4 + threads - 1) / threads;
    gelu_gate_kernel<<<blocks, threads>>>(
        (const float4*)x, log_alpha, log_sigma, (float4*)out, n4, surp);
}

// round 3
// speedup vs baseline: 1.1413x; 1.1413x over previous
#include <cuda_runtime.h>
#include <math.h>

// out = gelu_tanh(x) * gate
// gate = 1 + exp(log_alpha) * tanh(exp(log_sigma) * surp)
// surp = mean extremeness of double-argsort ranks = N/(2(N-1)), data-independent
//        (argsort(argsort) is always a permutation of 0..N-1 per column).
//
// gelu_tanh(x) = 0.5*x*(1+tanh(y)), y = sqrt(2/pi)*(x + 0.044715 x^3)
//              = x * sigmoid(2y) = x / (1 + exp(-2y))
// Computed with MUFU.EX2 + MUFU.RCP (fast approx, ~1e-6 rel err) instead of
// the slow accurate tanhf polynomial that was throttling issue slots.

__device__ __forceinline__ float gelu_fast(float x) {
    // -2 * sqrt(2/pi) * log2(e)
    const float kNeg2C0Log2e = -2.0f * 0.7978845608028654f * 1.4426950408889634f;
    const float c1 = 0.044715f;
    float x2 = x * x;
    float inner = fmaf(c1, x2, 1.0f) * x;       // x + c1*x^3
    float u = inner * kNeg2C0Log2e;             // -2*y * log2(e)
    float e = exp2f(u);                         // MUFU.EX2
    return __fdividef(x, e + 1.0f);             // x * MUFU.RCP(1+e)
}

__global__ void __launch_bounds__(256)
gelu_gate_kernel(const float4* __restrict__ x,
                 const float* __restrict__ log_alpha,
                 const float* __restrict__ log_sigma,
                 float4* __restrict__ out,
                 int n4, float surp) {
    int i = blockIdx.x * blockDim.x + threadIdx.x;
    if (i >= n4) return;

    // Uniform scalar loads: L1-broadcast, effectively free.
    float alpha = __expf(log_alpha[0]);
    float sigma = __expf(log_sigma[0]);
    float gate  = fmaf(alpha, tanhf(sigma * surp), 1.0f);

    float4 v = x[i];
    float4 r;
    r.x = gelu_fast(v.x) * gate;
    r.y = gelu_fast(v.y) * gate;
    r.z = gelu_fast(v.z) * gate;
    r.w = gelu_fast(v.w) * gate;
    out[i] = r;
}

extern "C" void kernel_launch(void* const* d_in, const int* in_sizes, int n_in,
                              void* d_out, int out_size) {
    const float* x         = (const float*)d_in[0];
    const float* log_alpha = (const float*)d_in[1];
    const float* log_sigma = (const float*)d_in[2];
    float* out             = (float*)d_out;

    long long n = in_sizes[0];          // B*T*D = 4*2048*4096
    const long long D = 4096;
    long long N = n / D;                // token count B*T = 8192
    float surp = (float)((double)N / (2.0 * (double)(N - 1)));

    int n4 = (int)(n / 4);
    int threads = 256;
    int blocks = (n4 + threads - 1) / threads;
    gelu_gate_kernel<<<blocks, threads>>>(
        (const float4*)x, log_alpha, log_sigma, (float4*)out, n4, surp);
}

// round 5
// speedup vs baseline: 1.1941x; 1.0463x over previous
#include <cuda_runtime.h>
#include <stdint.h>
#include <math.h>

// out = gelu_tanh(x) * gate
// gate = 1 + exp(log_alpha) * tanh(exp(log_sigma) * surp)
// surp = N/(2(N-1)) exactly (double-argsort ranks are always a permutation).
//
// gelu_tanh(x) = x / (1 + exp2(k * x * (1 + c1*x^2))), k = -2*sqrt(2/pi)*log2(e)
// ILP=4 float4 per thread: 4 batched LDG.128 -> ~24KB in flight per SM,
// enough to cover ~600cyc DRAM latency at the ~28 B/cyc/SM bandwidth need
// (previous 1-load/thread version had only ~6KB in flight -> DRAM stuck at 68%).

__device__ __forceinline__ float ex2_approx(float x) {
    float r; asm("ex2.approx.ftz.f32 %0, %1;" : "=f"(r) : "f"(x)); return r;
}
__device__ __forceinline__ float rcp_approx(float x) {
    float r; asm("rcp.approx.ftz.f32 %0, %1;" : "=f"(r) : "f"(x)); return r;
}

__device__ __forceinline__ float gelu_fast(float x, float gate) {
    const float kNeg2C0Log2e = -2.0f * 0.7978845608028654f * 1.4426950408889634f;
    const float c1 = 0.044715f;
    float x2 = x * x;
    float xk = x * kNeg2C0Log2e;
    float u  = fmaf(c1 * x2, xk, xk);        // k*x*(1 + c1*x^2)
    float e  = ex2_approx(u);
    return (x * gate) * rcp_approx(e + 1.0f);
}

#define ILP 4

__global__ void __launch_bounds__(256)
gelu_gate_kernel(const float4* __restrict__ x,
                 const float* __restrict__ log_alpha,
                 const float* __restrict__ log_sigma,
                 float4* __restrict__ out,
                 int n4, float surp) {
    int tid    = blockIdx.x * blockDim.x + threadIdx.x;
    int stride = gridDim.x * blockDim.x;

    float alpha = __expf(log_alpha[0]);
    float sigma = __expf(log_sigma[0]);
    float gate  = fmaf(alpha, tanhf(sigma * surp), 1.0f);

    // Batch all loads first: MLP = ILP outstanding LDG.128 per thread.
    float4 v[ILP];
    int   idx[ILP];
    bool  ok[ILP];
    #pragma unroll
    for (int k = 0; k < ILP; k++) {
        idx[k] = tid + k * stride;
        ok[k]  = idx[k] < n4;
        if (ok[k]) v[k] = x[idx[k]];
    }

    #pragma unroll
    for (int k = 0; k < ILP; k++) {
        if (ok[k]) {
            float4 r;
            r.x = gelu_fast(v[k].x, gate);
            r.y = gelu_fast(v[k].y, gate);
            r.z = gelu_fast(v[k].z, gate);
            r.w = gelu_fast(v[k].w, gate);
            out[idx[k]] = r;
        }
    }
}

extern "C" void kernel_launch(void* const* d_in, const int* in_sizes, int n_in,
                              void* d_out, int out_size) {
    const float* x         = (const float*)d_in[0];
    const float* log_alpha = (const float*)d_in[1];
    const float* log_sigma = (const float*)d_in[2];
    float* out             = (float*)d_out;

    long long n = in_sizes[0];          // B*T*D = 4*2048*4096
    const long long D = 4096;
    long long N = n / D;                // token count B*T = 8192
    float surp = (float)((double)N / (2.0 * (double)(N - 1)));

    int n4 = (int)(n / 4);
    int threads = 256;
    int blocks = (n4 + threads * ILP - 1) / (threads * ILP);
    gelu_gate_kernel<<<blocks, threads>>>(
        (const float4*)x, log_alpha, log_sigma, (float4*)out, n4, surp);
}